// round 3
// baseline (speedup 1.0000x reference)
#include <cuda_runtime.h>

// ComponentWiseSpline: rational-quadratic spline flow, forward + log|det J|.
// B=65536 rows, D=128 dims, K=8 bins.
// R3: warp-pair per row (lane owns 2 dims), register thresholds (14),
//     two conflict-free float4 smem tables (2 LDS.128/elem), x prefetch,
//     persistent grid 740 (=148 SMs x 5 blocks), end-of-block logdet combine.

#define BB 65536
#define DD 128
#define KK 8

#define WARPS   8
#define STREAMS 4                       // warp pairs per block
#define GRID    740                     // 148 * 5, single balanced wave
#define NSTREAM (GRID * STREAMS)        // 2960
#define MAXR    23                      // ceil(BB / NSTREAM)

__global__ void __launch_bounds__(256, 5)
spline_kernel(const float* __restrict__ x,
              const float* __restrict__ uw,
              const float* __restrict__ uh,
              const float* __restrict__ ud,
              float* __restrict__ uout,
              float* __restrict__ ldout) {
    __shared__ float4 sTA[KK * DD];          // 16 KB {invW, -cw*invW, cumH, H}
    __shared__ float4 sTB[KK * DD];          // 16 KB {delta, d0, d1, e}
    __shared__ float  sThr[(KK - 1) * DD];   // 3.5 KB thresholds (staging)
    __shared__ float  sPart[STREAMS][2][MAXR];

    const int tid  = threadIdx.x;
    const int lane = tid & 31;
    const int warp = tid >> 5;
    const int stream = warp >> 1;
    const int half   = warp & 1;

    // ---- per-block table build: thread d (<128) builds dim d ----
    if (tid < DD) {
        const int d = tid;
        const float BOUND = 3.0f;
        const float MINW = 1e-3f, MINH = 1e-3f, MIND = 1e-3f, EPS = 1e-6f;

        float w[KK], h[KK];
        float m = -1e30f;
        #pragma unroll
        for (int k = 0; k < KK; k++) { w[k] = uw[d * KK + k]; m = fmaxf(m, w[k]); }
        float s = 0.f;
        #pragma unroll
        for (int k = 0; k < KK; k++) { w[k] = expf(w[k] - m); s += w[k]; }
        float invs = 1.0f / s;
        #pragma unroll
        for (int k = 0; k < KK; k++) w[k] = MINW + (1.0f - MINW * KK) * (w[k] * invs);

        m = -1e30f;
        #pragma unroll
        for (int k = 0; k < KK; k++) { h[k] = uh[d * KK + k]; m = fmaxf(m, h[k]); }
        s = 0.f;
        #pragma unroll
        for (int k = 0; k < KK; k++) { h[k] = expf(h[k] - m); s += h[k]; }
        invs = 1.0f / s;
        #pragma unroll
        for (int k = 0; k < KK; k++) h[k] = MINH + (1.0f - MINH * KK) * (h[k] * invs);

        float cw[KK + 1], ch[KK + 1];
        cw[0] = -BOUND; ch[0] = -BOUND;
        float accw = 0.f, acch = 0.f;
        #pragma unroll
        for (int k = 1; k < KK; k++) {
            accw += w[k - 1]; cw[k] = fmaf(2.0f * BOUND, accw, -BOUND);
            acch += h[k - 1]; ch[k] = fmaf(2.0f * BOUND, acch, -BOUND);
        }
        cw[KK] = BOUND; ch[KK] = BOUND;

        float dv[KK + 1];
        dv[0] = 1.0f - MIND; dv[KK] = 1.0f - MIND;
        #pragma unroll
        for (int k = 1; k < KK; k++) {
            float v = ud[d * (KK - 1) + (k - 1)];
            dv[k] = MIND + fmaxf(v, 0.0f) + log1pf(expf(-fabsf(v)));
        }

        // slot: d = half*64 + 2*lane + c  ->  s = half*64 + c*32 + lane
        const int s_slot = ((d >> 6) << 6) + ((d & 1) << 5) + ((d >> 1) & 31);
        #pragma unroll
        for (int k = 0; k < KK; k++) {
            float W = cw[k + 1] - cw[k];
            float H = ch[k + 1] - ch[k];
            float invW = 1.0f / W;
            float del  = H * invW;
            sTA[k * DD + s_slot] = make_float4(invW, -cw[k] * invW, ch[k], H);
            sTB[k * DD + s_slot] = make_float4(del, dv[k], dv[k + 1],
                                               dv[k] + dv[k + 1] - 2.0f * del);
        }
        #pragma unroll
        for (int t = 0; t < KK - 1; t++)
            sThr[t * DD + s_slot] = cw[t + 1] + EPS;
    }
    __syncthreads();

    // ---- hoist this lane's 2x7 thresholds into registers ----
    float thr[2][KK - 1];
    #pragma unroll
    for (int c = 0; c < 2; c++) {
        const int s_slot = (half << 6) + (c << 5) + lane;
        #pragma unroll
        for (int t = 0; t < KK - 1; t++)
            thr[c][t] = sThr[t * DD + s_slot];
    }

    const int stream_gid = blockIdx.x * STREAMS + stream;   // 0..2959
    const size_t col = (size_t)(half << 6) + (lane << 1);   // dim offset of c=0

    int row = stream_gid;
    int ri = 0;
    if (row < BB) {
        float2 xv = *reinterpret_cast<const float2*>(x + (size_t)row * DD + col);
        while (true) {
            const int nrow = row + NSTREAM;
            float2 xnext;
            if (nrow < BB)
                xnext = *reinterpret_cast<const float2*>(x + (size_t)nrow * DD + col);

            float xin[2] = {xv.x, xv.y};
            float uo2[2];
            float lsum = 0.f;
            #pragma unroll
            for (int c = 0; c < 2; c++) {
                const float xi = xin[c];
                const float xc = fminf(fmaxf(xi, -3.0f), 3.0f);
                const bool inside = (xc == xi);

                int k = 0;
                #pragma unroll
                for (int t = 0; t < KK - 1; t++) k += (xc >= thr[c][t]);

                const int idx = k * DD + (half << 6) + (c << 5) + lane;
                const float4 A = sTA[idx];   // invW, -cw*invW, cumH, H
                const float4 Bv = sTB[idx];  // delta, d0, d1, e

                const float theta = fmaf(xc, A.x, A.y);
                const float omt  = 1.0f - theta;
                const float th2  = theta * theta;
                const float t1m  = theta * omt;
                const float omt2 = omt * omt;
                const float t1m2 = t1m + t1m;

                const float num    = A.w * fmaf(Bv.x, th2, Bv.y * t1m);
                const float den    = fmaf(Bv.w, t1m, Bv.x);
                const float invden = __fdividef(1.0f, den);
                const float uo     = fmaf(num, invden, A.z);

                const float inner = fmaf(Bv.z, th2, fmaf(Bv.x, t1m2, Bv.y * omt2));
                const float dnum  = (Bv.x * Bv.x) * inner;
                const float lad   = __logf(dnum * invden * invden);

                uo2[c] = inside ? uo : xi;
                lsum += inside ? lad : 0.0f;
            }

            *reinterpret_cast<float2*>(uout + (size_t)row * DD + col) =
                make_float2(uo2[0], uo2[1]);

            #pragma unroll
            for (int off = 16; off; off >>= 1)
                lsum += __shfl_xor_sync(0xffffffffu, lsum, off);
            if (lane == 0) sPart[stream][half][ri] = lsum;

            ri++;
            if (nrow >= BB) break;
            row = nrow;
            xv = xnext;
        }
    }
    __syncthreads();

    // ---- combine half-row partials and write log|det J| ----
    if (tid < STREAMS * MAXR) {
        const int st = tid / MAXR;
        const int i  = tid % MAXR;
        const int r  = blockIdx.x * STREAMS + st + i * NSTREAM;
        if (r < BB)
            ldout[r] = sPart[st][0][i] + sPart[st][1][i];
    }
}

extern "C" void kernel_launch(void* const* d_in, const int* in_sizes, int n_in,
                              void* d_out, int out_size) {
    const float* x  = (const float*)d_in[0];
    const float* uw = (const float*)d_in[1];
    const float* uh = (const float*)d_in[2];
    const float* ud = (const float*)d_in[3];
    float* out = (float*)d_out;

    spline_kernel<<<GRID, WARPS * 32>>>(
        x, uw, uh, ud, out, out + (size_t)BB * DD);
}

// round 4
// speedup vs baseline: 1.0881x; 1.0881x over previous
#include <cuda_runtime.h>

// ComponentWiseSpline: rational-quadratic spline flow, forward + log|det J|.
// B=65536 rows, D=128 dims, K=8 interior bins.
// R4: identity-extended 10-bin table (no clamp / no inside-select), FSET+FADD
//     bin search (off the ALU pipe), lane-owns-one-dim with 9 register
//     thresholds, 2 rows in flight per thread, persistent 148x4 grid.

#define BB 65536
#define DD 128
#define KK 8
#define NBINS 10                         // identity | 8 interior | identity
#define NPAIRS (BB / 2)                  // 32768 row-pairs
#define GRIDB 592                        // 148 SMs * 4 blocks
#define NS (GRIDB * 2)                   // 1184 row-pair streams (2 teams/block)
#define MAXP ((NPAIRS + NS - 1) / NS)    // 28

__device__ __forceinline__ float fsetge(float a, float b) {
    float r;
    asm("set.ge.f32.f32 %0, %1, %2;" : "=f"(r) : "f"(a), "f"(b));
    return r;
}

__global__ void __launch_bounds__(256, 4)
spline_kernel(const float* __restrict__ x,
              const float* __restrict__ uw,
              const float* __restrict__ uh,
              const float* __restrict__ ud,
              float* __restrict__ uout,
              float* __restrict__ ldout) {
    __shared__ float4 sTA[NBINS * DD];        // 20 KB {invW, -cw*invW, cumH, H}
    __shared__ float4 sTB[NBINS * DD];        // 20 KB {delta, d0, d1, e}
    __shared__ float  sThr[9 * DD];           // 4.5 KB
    __shared__ float  sPart[2][4][MAXP][2];   // 1.75 KB

    const int tid  = threadIdx.x;
    const int lane = tid & 31;
    const int warp = tid >> 5;
    const int team = warp >> 2;      // 0..1
    const int wslot = warp & 3;      // 0..3
    const int d = (wslot << 5) + lane;

    // ---- per-block table build: thread d (<128) builds dim d ----
    if (tid < DD) {
        const float BOUND = 3.0f;
        const float MINW = 1e-3f, MINH = 1e-3f, MIND = 1e-3f, EPS = 1e-6f;
        const int dd = tid;

        float w[KK], h[KK];
        float m = -1e30f;
        #pragma unroll
        for (int k = 0; k < KK; k++) { w[k] = uw[dd * KK + k]; m = fmaxf(m, w[k]); }
        float s = 0.f;
        #pragma unroll
        for (int k = 0; k < KK; k++) { w[k] = expf(w[k] - m); s += w[k]; }
        float invs = 1.0f / s;
        #pragma unroll
        for (int k = 0; k < KK; k++) w[k] = MINW + (1.0f - MINW * KK) * (w[k] * invs);

        m = -1e30f;
        #pragma unroll
        for (int k = 0; k < KK; k++) { h[k] = uh[dd * KK + k]; m = fmaxf(m, h[k]); }
        s = 0.f;
        #pragma unroll
        for (int k = 0; k < KK; k++) { h[k] = expf(h[k] - m); s += h[k]; }
        invs = 1.0f / s;
        #pragma unroll
        for (int k = 0; k < KK; k++) h[k] = MINH + (1.0f - MINH * KK) * (h[k] * invs);

        float cw[KK + 1], ch[KK + 1];
        cw[0] = -BOUND; ch[0] = -BOUND;
        float accw = 0.f, acch = 0.f;
        #pragma unroll
        for (int k = 1; k < KK; k++) {
            accw += w[k - 1]; cw[k] = fmaf(2.0f * BOUND, accw, -BOUND);
            acch += h[k - 1]; ch[k] = fmaf(2.0f * BOUND, acch, -BOUND);
        }
        cw[KK] = BOUND; ch[KK] = BOUND;

        float dv[KK + 1];
        dv[0] = 1.0f - MIND; dv[KK] = 1.0f - MIND;
        #pragma unroll
        for (int k = 1; k < KK; k++) {
            float v = ud[dd * (KK - 1) + (k - 1)];
            dv[k] = MIND + fmaxf(v, 0.0f) + log1pf(expf(-fabsf(v)));
        }

        // interior bins -> b = k+1
        #pragma unroll
        for (int k = 0; k < KK; k++) {
            float W = cw[k + 1] - cw[k];
            float H = ch[k + 1] - ch[k];
            float invW = 1.0f / W;
            float del  = H * invW;
            sTA[(k + 1) * DD + dd] = make_float4(invW, -cw[k] * invW, ch[k], H);
            sTB[(k + 1) * DD + dd] = make_float4(del, dv[k], dv[k + 1],
                                                 dv[k] + dv[k + 1] - 2.0f * del);
        }
        // identity bins b=0 (x < -3) and b=9 (x > 3):
        //   theta=x, num=theta, den=1, u=x; dnum=1, lad=0.
        const float4 idA = make_float4(1.0f, 0.0f, 0.0f, 1.0f);
        const float4 idB = make_float4(1.0f, 1.0f, 1.0f, 0.0f);
        sTA[0 * DD + dd] = idA; sTB[0 * DD + dd] = idB;
        sTA[9 * DD + dd] = idA; sTB[9 * DD + dd] = idB;

        // thresholds: T0=-3 (enter interior), T1..7 = cw[1..7]+EPS,
        // T8 = nextafter(3) (leave interior; x==3 stays in bin 7)
        sThr[0 * DD + dd] = -3.0f;
        #pragma unroll
        for (int t = 1; t < 8; t++) sThr[t * DD + dd] = cw[t] + EPS;
        sThr[8 * DD + dd] = __int_as_float(0x40400001);   // 3.0000002f
    }
    __syncthreads();

    // ---- this lane's 9 thresholds into registers ----
    float thr[9];
    #pragma unroll
    for (int j = 0; j < 9; j++) thr[j] = sThr[j * DD + d];

    const int S = blockIdx.x * 2 + team;    // stream id, 0..NS-1
    int p = S;                              // row-pair index: rows 2p, 2p+1
    const float* xp0 = x + (size_t)p * 256 + d;
    float xa = xp0[0];
    float xb = xp0[DD];
    int pi = 0;

    while (true) {
        const int np = p + NS;
        float xa2, xb2;
        if (np < NPAIRS) {
            const float* xq = x + (size_t)np * 256 + d;
            xa2 = xq[0];
            xb2 = xq[DD];
        }

        float uo[2], lads[2];
        float xin[2] = {xa, xb};
        #pragma unroll
        for (int e = 0; e < 2; e++) {
            const float xv = xin[e];
            // 10-way bin select: kf = #{j : xv >= thr[j]} in [0,9]
            float s0 = fsetge(xv, thr[0]) + fsetge(xv, thr[1]);
            float s1 = fsetge(xv, thr[2]) + fsetge(xv, thr[3]);
            float s2 = fsetge(xv, thr[4]) + fsetge(xv, thr[5]);
            float s3 = fsetge(xv, thr[6]) + fsetge(xv, thr[7]);
            float kf = ((s0 + s1) + (s2 + s3)) + fsetge(xv, thr[8]);
            const int idx = __float2int_rz(kf) * DD + d;

            const float4 A  = sTA[idx];   // invW, -cw*invW, cumH, H
            const float4 Bv = sTB[idx];   // delta, d0, d1, e

            const float theta = fmaf(xv, A.x, A.y);
            const float omt   = 1.0f - theta;
            const float th2   = theta * theta;
            const float t1m   = theta * omt;
            const float omt2  = omt * omt;
            const float t1m2  = t1m + t1m;

            const float num    = A.w * fmaf(Bv.x, th2, Bv.y * t1m);
            const float den    = fmaf(Bv.w, t1m, Bv.x);
            const float invden = __fdividef(1.0f, den);
            uo[e] = fmaf(num, invden, A.z);

            const float inner = fmaf(Bv.z, th2, fmaf(Bv.x, t1m2, Bv.y * omt2));
            const float dnum  = (Bv.x * Bv.x) * inner;
            lads[e] = __logf(dnum * (invden * invden));
        }

        float* up = uout + (size_t)p * 256 + d;
        up[0]  = uo[0];
        up[DD] = uo[1];

        float la = lads[0], lb = lads[1];
        #pragma unroll
        for (int off = 16; off; off >>= 1) {
            la += __shfl_xor_sync(0xffffffffu, la, off);
            lb += __shfl_xor_sync(0xffffffffu, lb, off);
        }
        if (lane == 0) {
            sPart[team][wslot][pi][0] = la;
            sPart[team][wslot][pi][1] = lb;
        }

        pi++;
        if (np >= NPAIRS) break;
        p = np;
        xa = xa2;
        xb = xb2;
    }
    __syncthreads();

    // ---- combine 4 warp-partials per row, write log|det J| ----
    if (tid < 2 * MAXP * 2) {
        const int tm   = tid / (MAXP * 2);
        const int rem  = tid - tm * (MAXP * 2);
        const int ppi  = rem >> 1;
        const int half = rem & 1;
        const int gp   = blockIdx.x * 2 + tm + ppi * NS;
        if (gp < NPAIRS) {
            float v = sPart[tm][0][ppi][half] + sPart[tm][1][ppi][half]
                    + sPart[tm][2][ppi][half] + sPart[tm][3][ppi][half];
            ldout[2 * gp + half] = v;
        }
    }
}

extern "C" void kernel_launch(void* const* d_in, const int* in_sizes, int n_in,
                              void* d_out, int out_size) {
    const float* x  = (const float*)d_in[0];
    const float* uw = (const float*)d_in[1];
    const float* uh = (const float*)d_in[2];
    const float* ud = (const float*)d_in[3];
    float* out = (float*)d_out;

    spline_kernel<<<GRIDB, 256>>>(x, uw, uh, ud, out, out + (size_t)BB * DD);
}